// round 8
// baseline (speedup 1.0000x reference)
#include <cuda_runtime.h>
#include <math_constants.h>

#define B_ 4
#define S_ 512
#define D_ 768
#define MAX_LEN_ 10
#define LEN_EMB_ 25
#define NUM_LABELS_ 9
#define N_ (S_ * MAX_LEN_)   // 5120

// len_logits[L-1][c] = len_emb_table[L-1] . W[768:, c] + b[c]
__device__ float g_len_logits[MAX_LEN_ * NUM_LABELS_];
// Transposed W head: Wt[c][d] = W[d][c]
__device__ __align__(16) float g_Wt[NUM_LABELS_][D_];

__global__ void prep_kernel(const float* __restrict__ len_emb_table,
                            const float* __restrict__ W,
                            const float* __restrict__ bvec) {
    int i = blockIdx.x * 256 + threadIdx.x;
    if (i < NUM_LABELS_ * D_) {
        int c = i / D_;
        int d = i % D_;
        g_Wt[c][d] = W[(size_t)d * NUM_LABELS_ + c];
    }
    if (blockIdx.x == 0 && threadIdx.x < MAX_LEN_ * NUM_LABELS_) {
        int L = threadIdx.x / NUM_LABELS_;
        int c = threadIdx.x % NUM_LABELS_;
        float s = bvec[c];
        #pragma unroll
        for (int k = 0; k < LEN_EMB_; k++) {
            s = fmaf(len_emb_table[L * LEN_EMB_ + k], W[(D_ + k) * NUM_LABELS_ + c], s);
        }
        g_len_logits[threadIdx.x] = s;
    }
}

__device__ __forceinline__ float4 max4(float4 a, float4 b) {
    float4 r;
    r.x = fmaxf(a.x, b.x); r.y = fmaxf(a.y, b.y);
    r.z = fmaxf(a.z, b.z); r.w = fmaxf(a.w, b.w);
    return r;
}

__device__ __forceinline__ unsigned long long pack2(float lo, float hi) {
    unsigned long long r;
    asm("mov.b64 %0, {%1, %2};" : "=l"(r) : "f"(lo), "f"(hi));
    return r;
}
__device__ __forceinline__ void fma2(unsigned long long& d,
                                     unsigned long long a, unsigned long long b) {
    asm("fma.rn.f32x2 %0, %1, %2, %0;" : "+l"(d) : "l"(a), "l"(b));
}
__device__ __forceinline__ float hsum2(unsigned long long v) {
    float lo, hi;
    asm("mov.b64 {%0, %1}, %2;" : "=f"(lo), "=f"(hi) : "l"(v));
    return lo + hi;
}

// One 192-thread block per (batch, start); warp = (csplit, half):
//   csplit = wid>>1 owns columns [3*csplit, 3*csplit+3)
//   half   = wid&1  owns dims [384*half, 384*half+384), 12 dims/lane.
// Fused streaming: warp reads its half of the 10 clamped rows, keeps the
// running prefix-max, emits 3 packed-f32x2 dot partials per span. The two
// halves of a column-triple meet in a 64-wide conflict-free smem
// transpose-reduce (stride 68 words). One __syncthreads total; no shuffles.
__global__ __launch_bounds__(192, 4) void span_ner_kernel(
    const float* __restrict__ we,       // [B, S, D]
    const int*   __restrict__ starts,   // [B, N]
    const int*   __restrict__ lens,     // [B, N]
    float*       __restrict__ out)      // [B, N, 9]
{
    __shared__ float redw_s[3][30][68]; // per column-triple scratch, 24.5 KB

    const int lane   = threadIdx.x & 31;
    const int wid    = threadIdx.x >> 5;
    const int half   = wid & 1;
    const int csplit = wid >> 1;
    const int c0     = csplit * 3;
    float* const redw = &redw_s[csplit][0][0];

    // W slice, packed f32x2: lane owns dims 384*half + 4*(lane+32k), k in [0,3).
    unsigned long long Wp[3][3][2];
    #pragma unroll
    for (int k = 0; k < 3; k++) {
        #pragma unroll
        for (int t = 0; t < 3; t++) {
            float4 w = *(const float4*)&g_Wt[c0 + t][384 * half + 4 * (lane + 32 * k)];
            Wp[k][t][0] = pack2(w.x, w.y);
            Wp[k][t][1] = pack2(w.z, w.w);
        }
    }

    const int bs = blockIdx.x;
    const int b = bs >> 9;               // /512
    const int s = bs & (S_ - 1);

    const size_t bn = (size_t)b * N_ + (size_t)s * MAX_LEN_;
    const int start = starts[bn];
    const int smax1 = S_ - start - 1;    // >= 0
    const float* base = we + ((size_t)b * S_ + start) * D_ + 384 * half;

    float4 m[3];
    #pragma unroll
    for (int k = 0; k < 3; k++)
        m[k] = make_float4(-CUDART_INF_F, -CUDART_INF_F, -CUDART_INF_F, -CUDART_INF_F);

    // pooled(j) = prefix max through clamped row j (clamped dups idempotent).
    #pragma unroll
    for (int r = 0; r < MAX_LEN_; r++) {
        const int rc = (r < smax1) ? r : smax1;
        const float* rowp = base + (size_t)rc * D_;
        float4 v[3];
        #pragma unroll
        for (int k = 0; k < 3; k++)
            v[k] = __ldg((const float4*)(rowp + 4 * (lane + 32 * k)));
        #pragma unroll
        for (int k = 0; k < 3; k++)
            m[k] = max4(m[k], v[k]);

        unsigned long long A0 = 0ull, A1 = 0ull, A2 = 0ull;
        #pragma unroll
        for (int k = 0; k < 3; k++) {
            const unsigned long long p0 = pack2(m[k].x, m[k].y);
            const unsigned long long p1 = pack2(m[k].z, m[k].w);
            fma2(A0, p0, Wp[k][0][0]); fma2(A0, p1, Wp[k][0][1]);
            fma2(A1, p0, Wp[k][1][0]); fma2(A1, p1, Wp[k][1][1]);
            fma2(A2, p0, Wp[k][2][0]); fma2(A2, p1, Wp[k][2][1]);
        }
        // span j = r partials; halves interleave at word offsets [0,32)+[32,64).
        const int col = 32 * half + lane;            // conflict-free STS.32
        redw[(3 * r + 0) * 68 + col] = hsum2(A0);
        redw[(3 * r + 1) * 68 + col] = hsum2(A1);
        redw[(3 * r + 2) * 68 + col] = hsum2(A2);
    }
    __syncthreads();   // join the two halves of each column-triple

    // Transpose-reduce: half-0 warps, lane < 30 sums its (j,t) row of 64
    // partials. Row stride 68 words = 17 x 16B granules (odd) -> LDS.128
    // conflict-free.
    if (half == 0 && lane < 30) {
        const float4* rp = (const float4*)(redw + lane * 68);
        float4 t0 = rp[0], t1 = rp[1], t2 = rp[2], t3 = rp[3];
        float4 t4 = rp[4], t5 = rp[5], t6 = rp[6], t7 = rp[7];
        float4 u0 = rp[8], u1 = rp[9], u2 = rp[10], u3 = rp[11];
        float4 u4 = rp[12], u5 = rp[13], u6 = rp[14], u7 = rp[15];
        t0 = make_float4(t0.x + u0.x, t0.y + u0.y, t0.z + u0.z, t0.w + u0.w);
        t1 = make_float4(t1.x + u1.x, t1.y + u1.y, t1.z + u1.z, t1.w + u1.w);
        t2 = make_float4(t2.x + u2.x, t2.y + u2.y, t2.z + u2.z, t2.w + u2.w);
        t3 = make_float4(t3.x + u3.x, t3.y + u3.y, t3.z + u3.z, t3.w + u3.w);
        t4 = make_float4(t4.x + u4.x, t4.y + u4.y, t4.z + u4.z, t4.w + u4.w);
        t5 = make_float4(t5.x + u5.x, t5.y + u5.y, t5.z + u5.z, t5.w + u5.w);
        t6 = make_float4(t6.x + u6.x, t6.y + u6.y, t6.z + u6.z, t6.w + u6.w);
        t7 = make_float4(t7.x + u7.x, t7.y + u7.y, t7.z + u7.z, t7.w + u7.w);
        t0 = make_float4(t0.x + t4.x, t0.y + t4.y, t0.z + t4.z, t0.w + t4.w);
        t1 = make_float4(t1.x + t5.x, t1.y + t5.y, t1.z + t5.z, t1.w + t5.w);
        t2 = make_float4(t2.x + t6.x, t2.y + t6.y, t2.z + t6.z, t2.w + t6.w);
        t3 = make_float4(t3.x + t7.x, t3.y + t7.y, t3.z + t7.z, t3.w + t7.w);
        t0 = make_float4(t0.x + t2.x, t0.y + t2.y, t0.z + t2.z, t0.w + t2.w);
        t1 = make_float4(t1.x + t3.x, t1.y + t3.y, t1.z + t3.z, t1.w + t3.w);
        const float tot = (t0.x + t1.x) + (t0.y + t1.y) + (t0.z + t1.z) + (t0.w + t1.w);

        const int j = lane / 3;
        const int t = lane - 3 * j;
        const int L = __ldg(lens + bn + j);
        out[(bn + j) * NUM_LABELS_ + c0 + t] =
            tot + g_len_logits[(L - 1) * NUM_LABELS_ + c0 + t];
    }
}

extern "C" void kernel_launch(void* const* d_in, const int* in_sizes, int n_in,
                              void* d_out, int out_size) {
    const float* we     = (const float*)d_in[0];   // word_embeddings [B,S,D]
    const int*   starts = (const int*)d_in[1];     // span_starts [B,N]
    const int*   lens   = (const int*)d_in[2];     // span_lens [B,N]
    const float* let    = (const float*)d_in[3];   // len_emb_table [MAX_LEN, LEN_EMB]
    const float* W      = (const float*)d_in[4];   // W [D+LEN_EMB, 9]
    const float* bvec   = (const float*)d_in[5];   // b [9]
    float* out = (float*)d_out;

    prep_kernel<<<(NUM_LABELS_ * D_ + 255) / 256, 256>>>(let, W, bvec);

    span_ner_kernel<<<B_ * S_, 192>>>(we, starts, lens, out);
}

// round 10
// speedup vs baseline: 1.6209x; 1.6209x over previous
#include <cuda_runtime.h>
#include <math_constants.h>

#define B_ 4
#define S_ 512
#define D_ 768
#define MAX_LEN_ 10
#define LEN_EMB_ 25
#define NUM_LABELS_ 9
#define N_ (S_ * MAX_LEN_)   // 5120
#define RED_STRIDE 100       // 96 partials + pad; 4*o mod 32 distinct per 8-lane phase

// len_logits[L-1][c] = len_emb_table[L-1] . W[768:, c] + b[c]
__device__ float g_len_logits[MAX_LEN_ * NUM_LABELS_];
// Transposed W head: Wt[c][d] = W[d][c]
__device__ __align__(16) float g_Wt[NUM_LABELS_][D_];

__global__ void prep_kernel(const float* __restrict__ len_emb_table,
                            const float* __restrict__ W,
                            const float* __restrict__ bvec) {
    int i = blockIdx.x * 256 + threadIdx.x;
    if (i < NUM_LABELS_ * D_) {
        int c = i / D_;
        int d = i % D_;
        g_Wt[c][d] = W[(size_t)d * NUM_LABELS_ + c];
    }
    if (blockIdx.x == 0 && threadIdx.x < MAX_LEN_ * NUM_LABELS_) {
        int L = threadIdx.x / NUM_LABELS_;
        int c = threadIdx.x % NUM_LABELS_;
        float s = bvec[c];
        #pragma unroll
        for (int k = 0; k < LEN_EMB_; k++) {
            s = fmaf(len_emb_table[L * LEN_EMB_ + k], W[(D_ + k) * NUM_LABELS_ + c], s);
        }
        g_len_logits[threadIdx.x] = s;
    }
}

__device__ __forceinline__ float4 max4(float4 a, float4 b) {
    float4 r;
    r.x = fmaxf(a.x, b.x); r.y = fmaxf(a.y, b.y);
    r.z = fmaxf(a.z, b.z); r.w = fmaxf(a.w, b.w);
    return r;
}

__device__ __forceinline__ unsigned long long pack2(float lo, float hi) {
    unsigned long long r;
    asm("mov.b64 %0, {%1, %2};" : "=l"(r) : "f"(lo), "f"(hi));
    return r;
}
__device__ __forceinline__ unsigned long long mul2(unsigned long long a,
                                                   unsigned long long b) {
    unsigned long long r;
    asm("mul.rn.f32x2 %0, %1, %2;" : "=l"(r) : "l"(a), "l"(b));
    return r;
}
__device__ __forceinline__ void fma2(unsigned long long& d,
                                     unsigned long long a, unsigned long long b) {
    asm("fma.rn.f32x2 %0, %1, %2, %0;" : "+l"(d) : "l"(a), "l"(b));
}
__device__ __forceinline__ float hsum2(unsigned long long v) {
    float lo, hi;
    asm("mov.b64 {%0, %1}, %2;" : "=f"(lo), "=f"(hi) : "l"(v));
    return lo + hi;
}

// One 96-thread block per (batch, start). Pure D-split: warp w owns dims
// [256w, 256w+256) (8 dims/lane as 2 float4), computes ALL 9 columns over its
// third. Each we row is read ONCE per block. Per row: update running
// prefix-max, recompute the 9 per-lane dot partials FROM ZERO (mul2 + 3 fma2),
// snapshot them with 9 conflict-free STS.32 into red[90][100]. One
// __syncthreads, then a conflict-free 96-wide transpose-reduce. Zero shuffles.
__global__ __launch_bounds__(96) void span_ner_kernel(
    const float* __restrict__ we,       // [B, S, D]
    const int*   __restrict__ starts,   // [B, N]
    const int*   __restrict__ lens,     // [B, N]
    float*       __restrict__ out)      // [B, N, 9]
{
    __shared__ float red[MAX_LEN_ * NUM_LABELS_][RED_STRIDE];  // 36 KB

    const int lane = threadIdx.x & 31;
    const int wid  = threadIdx.x >> 5;

    // Lane's dims: d0 = 256*wid + 4*lane (float4), and d0 + 128 (float4).
    const int d0 = 256 * wid + 4 * lane;

    // W slice packed f32x2: 9 cols x 4 u64 = 36 u64 (72 regs).
    unsigned long long Wp[NUM_LABELS_][4];
    #pragma unroll
    for (int c = 0; c < NUM_LABELS_; c++) {
        float4 wa = *(const float4*)&g_Wt[c][d0];
        float4 wb = *(const float4*)&g_Wt[c][d0 + 128];
        Wp[c][0] = pack2(wa.x, wa.y);
        Wp[c][1] = pack2(wa.z, wa.w);
        Wp[c][2] = pack2(wb.x, wb.y);
        Wp[c][3] = pack2(wb.z, wb.w);
    }

    const int bs = blockIdx.x;
    const int b = bs >> 9;               // /512
    const int s = bs & (S_ - 1);

    const size_t bn = (size_t)b * N_ + (size_t)s * MAX_LEN_;
    const int start = starts[bn];
    const int smax1 = S_ - start - 1;    // >= 0
    const float* base = we + ((size_t)b * S_ + start) * D_ + d0;

    float4 m0 = make_float4(-CUDART_INF_F, -CUDART_INF_F, -CUDART_INF_F, -CUDART_INF_F);
    float4 m1 = m0;

    const int t96 = 32 * wid + lane;     // partial column index 0..95

    // pooled(j) = prefix max through clamped row j (clamped dups idempotent
    // under max, matching lens[j] = min(j+1, S-start)).
    #pragma unroll
    for (int r = 0; r < MAX_LEN_; r++) {
        const int rc = (r < smax1) ? r : smax1;
        const float* rowp = base + (size_t)rc * D_;
        float4 v0 = __ldg((const float4*)rowp);
        float4 v1 = __ldg((const float4*)(rowp + 128));
        m0 = max4(m0, v0);
        m1 = max4(m1, v1);

        const unsigned long long p0 = pack2(m0.x, m0.y);
        const unsigned long long p1 = pack2(m0.z, m0.w);
        const unsigned long long p2 = pack2(m1.x, m1.y);
        const unsigned long long p3 = pack2(m1.z, m1.w);

        // Per-row dot partials, recomputed from zero each row.
        #pragma unroll
        for (int c = 0; c < NUM_LABELS_; c++) {
            unsigned long long a = mul2(p0, Wp[c][0]);
            fma2(a, p1, Wp[c][1]);
            fma2(a, p2, Wp[c][2]);
            fma2(a, p3, Wp[c][3]);
            red[r * NUM_LABELS_ + c][t96] = hsum2(a);   // conflict-free STS.32
        }
    }
    __syncthreads();

    // Transpose-reduce: output o = wid*30 + lane (lane < 30) sums its row of
    // 96 partials. Starts 4*o mod 32 are distinct within each 8-lane phase ->
    // LDS.128 at the 4-cyc floor.
    if (lane < 30) {
        const int o = wid * 30 + lane;                   // 0..89 = j*9 + c
        const float4* rp = (const float4*)red[o];
        float4 t0 = rp[0], t1 = rp[1], t2 = rp[2], t3 = rp[3];
        float4 t4 = rp[4], t5 = rp[5], t6 = rp[6], t7 = rp[7];
        #pragma unroll
        for (int g = 8; g < 24; g += 8) {
            float4 u0 = rp[g], u1 = rp[g+1], u2 = rp[g+2], u3 = rp[g+3];
            float4 u4 = rp[g+4], u5 = rp[g+5], u6 = rp[g+6], u7 = rp[g+7];
            t0 = make_float4(t0.x + u0.x, t0.y + u0.y, t0.z + u0.z, t0.w + u0.w);
            t1 = make_float4(t1.x + u1.x, t1.y + u1.y, t1.z + u1.z, t1.w + u1.w);
            t2 = make_float4(t2.x + u2.x, t2.y + u2.y, t2.z + u2.z, t2.w + u2.w);
            t3 = make_float4(t3.x + u3.x, t3.y + u3.y, t3.z + u3.z, t3.w + u3.w);
            t4 = make_float4(t4.x + u4.x, t4.y + u4.y, t4.z + u4.z, t4.w + u4.w);
            t5 = make_float4(t5.x + u5.x, t5.y + u5.y, t5.z + u5.z, t5.w + u5.w);
            t6 = make_float4(t6.x + u6.x, t6.y + u6.y, t6.z + u6.z, t6.w + u6.w);
            t7 = make_float4(t7.x + u7.x, t7.y + u7.y, t7.z + u7.z, t7.w + u7.w);
        }
        t0 = make_float4(t0.x + t4.x, t0.y + t4.y, t0.z + t4.z, t0.w + t4.w);
        t1 = make_float4(t1.x + t5.x, t1.y + t5.y, t1.z + t5.z, t1.w + t5.w);
        t2 = make_float4(t2.x + t6.x, t2.y + t6.y, t2.z + t6.z, t2.w + t6.w);
        t3 = make_float4(t3.x + t7.x, t3.y + t7.y, t3.z + t7.z, t3.w + t7.w);
        t0 = make_float4(t0.x + t2.x, t0.y + t2.y, t0.z + t2.z, t0.w + t2.w);
        t1 = make_float4(t1.x + t3.x, t1.y + t3.y, t1.z + t3.z, t1.w + t3.w);
        const float tot = (t0.x + t1.x) + (t0.y + t1.y) + (t0.z + t1.z) + (t0.w + t1.w);

        const int j = o / NUM_LABELS_;
        const int c = o - NUM_LABELS_ * j;
        const int L = __ldg(lens + bn + j);
        out[bn * NUM_LABELS_ + o] = tot + g_len_logits[(L - 1) * NUM_LABELS_ + c];
    }
}

extern "C" void kernel_launch(void* const* d_in, const int* in_sizes, int n_in,
                              void* d_out, int out_size) {
    const float* we     = (const float*)d_in[0];   // word_embeddings [B,S,D]
    const int*   starts = (const int*)d_in[1];     // span_starts [B,N]
    const int*   lens   = (const int*)d_in[2];     // span_lens [B,N]
    const float* let    = (const float*)d_in[3];   // len_emb_table [MAX_LEN, LEN_EMB]
    const float* W      = (const float*)d_in[4];   // W [D+LEN_EMB, 9]
    const float* bvec   = (const float*)d_in[5];   // b [9]
    float* out = (float*)d_out;

    prep_kernel<<<(NUM_LABELS_ * D_ + 255) / 256, 256>>>(let, W, bvec);

    span_ner_kernel<<<B_ * S_, 96>>>(we, starts, lens, out);
}